// round 1
// baseline (speedup 1.0000x reference)
#include <cuda_runtime.h>

#define A_COEF 0.01f
#define B_COEF 4.81f
#define C_COEF 0.0f
#define OOB_COST 3.0f

__device__ __forceinline__ float penal(float v) {
    float cost = C_COEF + A_COEF * __expf(B_COEF * (1.0f + v));
    bool in_bounds = (v >= 0.0f) && (v <= 1.0f);
    return in_bounds ? cost : OOB_COST;
}

__global__ void __launch_bounds__(256) penalizer_kernel(
    const float* __restrict__ X, float* __restrict__ out, int n_rows)
{
    // Each thread handles 4 consecutive rows -> one float4 store.
    int t = blockIdx.x * blockDim.x + threadIdx.x;
    int base = t * 4;
    if (base + 3 < n_rows) {
        // 4 independent loads, stride 32B each (one per 32B sector).
        float v0 = X[(size_t)(base + 0) * 8 + 7];
        float v1 = X[(size_t)(base + 1) * 8 + 7];
        float v2 = X[(size_t)(base + 2) * 8 + 7];
        float v3 = X[(size_t)(base + 3) * 8 + 7];
        float4 r;
        r.x = penal(v0);
        r.y = penal(v1);
        r.z = penal(v2);
        r.w = penal(v3);
        reinterpret_cast<float4*>(out)[t] = r;
    } else {
        // tail (not hit for N % 4 == 0, but stay correct generally)
        for (int i = base; i < n_rows; ++i) {
            out[i] = penal(X[(size_t)i * 8 + 7]);
        }
    }
}

extern "C" void kernel_launch(void* const* d_in, const int* in_sizes, int n_in,
                              void* d_out, int out_size)
{
    const float* X = (const float*)d_in[0];
    float* out = (float*)d_out;
    int n_rows = in_sizes[0] / 8;          // [N, 8] fp32
    int n_threads = (n_rows + 3) / 4;
    int block = 256;
    int grid = (n_threads + block - 1) / block;
    penalizer_kernel<<<grid, block>>>(X, out, n_rows);
}

// round 2
// speedup vs baseline: 1.0325x; 1.0325x over previous
#include <cuda_runtime.h>

#define A_COEF 0.01f
#define B_COEF 4.81f
#define C_COEF 0.0f
#define OOB_COST 3.0f

#define ROWS_PER_THREAD 8

__device__ __forceinline__ float penal(float v) {
    float cost = C_COEF + A_COEF * __expf(B_COEF * (1.0f + v));
    bool in_bounds = (v >= 0.0f) && (v <= 1.0f);
    return in_bounds ? cost : OOB_COST;
}

__global__ void __launch_bounds__(256) penalizer_kernel(
    const float* __restrict__ X, float* __restrict__ out, int n_rows)
{
    int t = blockIdx.x * blockDim.x + threadIdx.x;
    long long base = (long long)t * ROWS_PER_THREAD;

    if (base + ROWS_PER_THREAD - 1 < n_rows) {
        // 8 independent streaming loads, front-batched for max MLP.
        float v[ROWS_PER_THREAD];
        #pragma unroll
        for (int i = 0; i < ROWS_PER_THREAD; ++i) {
            v[i] = __ldcs(X + (base + i) * 8 + 7);
        }
        float4 r0, r1;
        r0.x = penal(v[0]); r0.y = penal(v[1]); r0.z = penal(v[2]); r0.w = penal(v[3]);
        r1.x = penal(v[4]); r1.y = penal(v[5]); r1.z = penal(v[6]); r1.w = penal(v[7]);
        float4* o4 = reinterpret_cast<float4*>(out) + (long long)t * 2;
        __stcs(o4 + 0, r0);
        __stcs(o4 + 1, r1);
    } else {
        // tail (not hit when N % 8 == 0, but stay correct generally)
        for (long long i = base; i < n_rows; ++i) {
            out[i] = penal(__ldcs(X + i * 8 + 7));
        }
    }
}

extern "C" void kernel_launch(void* const* d_in, const int* in_sizes, int n_in,
                              void* d_out, int out_size)
{
    const float* X = (const float*)d_in[0];
    float* out = (float*)d_out;
    int n_rows = in_sizes[0] / 8;          // [N, 8] fp32
    int n_threads = (n_rows + ROWS_PER_THREAD - 1) / ROWS_PER_THREAD;
    int block = 256;
    int grid = (n_threads + block - 1) / block;
    penalizer_kernel<<<grid, block>>>(X, out, n_rows);
}